// round 5
// baseline (speedup 1.0000x reference)
#include <cuda_runtime.h>
#include <cuda_bf16.h>
#include <cstdint>

// ---------------------------------------------------------------------------
// total = -(1/L) * sum_i dot(q_hat_i, q_real_i)
//       + sum_{i,j} max(0, <pred_i, gt_j> - <pred_i, gt_i> + 1)
// L=8192, B=4096, D=1024.
// R5: GEMM pred @ gt^T in INT8 (s8 x s8 -> s32, exact accumulation) via
// mma.sync.m16n8k32. ~3x lower quantization error than e4m3. local_kernel
// forked onto a side stream to overlap with the GEMM inside the graph.
// ---------------------------------------------------------------------------

#define L_DIM 8192
#define B_DIM 4096
#define D_DIM 1024

// int8 quantization scale: clip at 4 sigma (inputs ~ N(0,1))
#define QSCALE 31.75f

__device__ double g_glob;
__device__ double g_local;
__device__ float g_pos[B_DIM];
// int8 operand buffers (4 MB each), stored as uint32 (4 s8 per word)
__device__ uint32_t g_predq[(size_t)B_DIM * D_DIM / 4];
__device__ uint32_t g_gtq[(size_t)B_DIM * D_DIM / 4];

// ---------------------------------------------------------------------------
__device__ __forceinline__ uint32_t smem_u32(const void* p) {
    uint32_t a;
    asm("{ .reg .u64 t; cvta.to.shared.u64 t, %1; cvt.u32.u64 %0, t; }"
        : "=r"(a) : "l"(p));
    return a;
}

__device__ __forceinline__ void cp_async16(uint32_t smem, const void* gmem) {
    asm volatile("cp.async.cg.shared.global [%0], [%1], 16;"
                 :: "r"(smem), "l"(gmem) : "memory");
}
#define CP_COMMIT() asm volatile("cp.async.commit_group;" ::: "memory")
#define CP_WAIT1()  asm volatile("cp.async.wait_group 1;" ::: "memory")

#define LDSM_X4(r0, r1, r2, r3, addr) \
    asm volatile("ldmatrix.sync.aligned.m8n8.x4.shared.b16 {%0,%1,%2,%3}, [%4];" \
                 : "=r"(r0), "=r"(r1), "=r"(r2), "=r"(r3) : "r"(addr))

// INT8 MMA, k32, exact s32 accumulation. Fragment layout identical to the
// 8-bit fp8 variant (each b16 lane element = 2 consecutive-k bytes).
__device__ __forceinline__ void mma16832_s8(int32_t* c, const uint32_t* a,
                                            uint32_t b0, uint32_t b1) {
    asm volatile(
        "mma.sync.aligned.m16n8k32.row.col.s32.s8.s8.s32 "
        "{%0,%1,%2,%3}, {%4,%5,%6,%7}, {%8,%9}, {%0,%1,%2,%3};"
        : "+r"(c[0]), "+r"(c[1]), "+r"(c[2]), "+r"(c[3])
        : "r"(a[0]), "r"(a[1]), "r"(a[2]), "r"(a[3]), "r"(b0), "r"(b1));
}

__device__ __forceinline__ int quant_s8(float x) {
    return (int)__float2int_rn(fminf(fmaxf(x * QSCALE, -127.f), 127.f));
}

__device__ __forceinline__ uint32_t pack_s8x4(float4 v) {
    const int i0 = quant_s8(v.x), i1 = quant_s8(v.y);
    const int i2 = quant_s8(v.z), i3 = quant_s8(v.w);
    return (uint32_t)(i0 & 0xff) | ((uint32_t)(i1 & 0xff) << 8) |
           ((uint32_t)(i2 & 0xff) << 16) | ((uint32_t)(i3 & 0xff) << 24);
}

// ---------------------------------------------------------------------------
// Kernel 0: zero accumulators (must precede the forked local_kernel)
// ---------------------------------------------------------------------------
__global__ void zero_kernel() {
    g_glob = 0.0;
    g_local = 0.0;
}

// ---------------------------------------------------------------------------
// Kernel 1: fp32 -> s8 quantize for pred/gt + pos[i] = dot(pred_i, gt_i)
// (pos stays exact fp32). grid = B_DIM x 256, one float4 per thread.
// ---------------------------------------------------------------------------
__global__ void prep_kernel(const float* __restrict__ pred,
                            const float* __restrict__ gt) {
    const int r = blockIdx.x;
    const int t = threadIdx.x;
    const float4 pv = ((const float4*)(pred + (size_t)r * D_DIM))[t];
    const float4 gv = ((const float4*)(gt + (size_t)r * D_DIM))[t];

    float acc = pv.x * gv.x + pv.y * gv.y + pv.z * gv.z + pv.w * gv.w;

    g_predq[(size_t)r * (D_DIM / 4) + t] = pack_s8x4(pv);
    g_gtq[(size_t)r * (D_DIM / 4) + t] = pack_s8x4(gv);

    #pragma unroll
    for (int o = 16; o > 0; o >>= 1)
        acc += __shfl_xor_sync(0xFFFFFFFFu, acc, o);
    __shared__ float ws[8];
    if ((t & 31) == 0) ws[t >> 5] = acc;
    __syncthreads();
    if (t == 0) {
        float s = 0.f;
        #pragma unroll
        for (int w = 0; w < 8; w++) s += ws[w];
        g_pos[r] = s;
    }
}

// ---------------------------------------------------------------------------
// Kernel 2: local loss partial:  g_local += sum(q_hat * q_real)
// (runs on a side stream, overlapped with prep + GEMM)
// ---------------------------------------------------------------------------
__global__ void local_kernel(const float* __restrict__ a,
                             const float* __restrict__ b) {
    const size_t n4 = (size_t)L_DIM * D_DIM / 4;
    float acc = 0.f;
    for (size_t i = (size_t)blockIdx.x * blockDim.x + threadIdx.x; i < n4;
         i += (size_t)gridDim.x * blockDim.x) {
        float4 av = ((const float4*)a)[i];
        float4 bv = ((const float4*)b)[i];
        acc += av.x * bv.x + av.y * bv.y + av.z * bv.z + av.w * bv.w;
    }
    #pragma unroll
    for (int o = 16; o > 0; o >>= 1)
        acc += __shfl_xor_sync(0xFFFFFFFFu, acc, o);
    __shared__ float ws[8];
    const int t = threadIdx.x;
    if ((t & 31) == 0) ws[t >> 5] = acc;
    __syncthreads();
    if (t == 0) {
        float s = 0.f;
        #pragma unroll
        for (int w = 0; w < 8; w++) s += ws[w];
        atomicAdd(&g_local, (double)s);
    }
}

// ---------------------------------------------------------------------------
// Kernel 3: INT8 GEMM 128x128 tile via mma.sync.m16n8k32 + fused hinge.
// grid = (32, 32), 256 threads (8 warps: 2(m) x 4(n), warp tile 64x32).
// BK = 128 s8 = 128 B/row -> 16 KB per operand stage, 3 stages, 8 K-chunks.
// XOR swizzle (8 x 16B chunks per 128 B row). 2 CTAs/SM.
// ---------------------------------------------------------------------------
static constexpr int GEMM_SMEM_DYN = 3 * 32768;  // 96 KB

__global__ void __launch_bounds__(256, 2) gemm_hinge_kernel() {
    extern __shared__ char smem_raw[];
    const uint32_t sb = smem_u32(smem_raw);
    const int tid = threadIdx.x;
    const int wid = tid >> 5;
    const int lane = tid & 31;
    const int warp_m = wid >> 2;   // 0..1
    const int warp_n = wid & 3;    // 0..3

    const uint8_t* __restrict__ Ab =
        (const uint8_t*)g_predq + (size_t)blockIdx.y * 128 * D_DIM;
    const uint8_t* __restrict__ Bb =
        (const uint8_t*)g_gtq + (size_t)blockIdx.x * 128 * D_DIM;

    int32_t acc[4][4][4];
    #pragma unroll
    for (int i = 0; i < 4; i++)
        #pragma unroll
        for (int j = 0; j < 4; j++)
            #pragma unroll
            for (int e = 0; e < 4; e++) acc[i][j][e] = 0;

    // Load one K-chunk (128 s8 = 128 B per row) of A and B into stage st.
    auto load_stage = [&](int kc, int st) {
        const uint32_t baseA = sb + st * 32768;
        const uint32_t baseB = baseA + 16384;
        #pragma unroll
        for (int i = 0; i < 4; i++) {
            const int idx = tid + i * 256;      // 0..1023
            const int row = idx >> 3;           // 0..127
            const int c = idx & 7;              // 16B chunk within 128B row
            const uint32_t soff = row * 128 + ((c ^ (row & 7)) << 4);
            cp_async16(baseA + soff, Ab + (size_t)row * D_DIM + kc * 128 + c * 16);
            cp_async16(baseB + soff, Bb + (size_t)row * D_DIM + kc * 128 + c * 16);
        }
    };

    load_stage(0, 0); CP_COMMIT();
    load_stage(1, 1); CP_COMMIT();

    #pragma unroll 1
    for (int kc = 0; kc < 8; ++kc) {
        CP_WAIT1();          // stage kc resident
        __syncthreads();     // all warps done with the stage we refill
        if (kc + 2 < 8) load_stage(kc + 2, (kc + 2) % 3);
        CP_COMMIT();         // uniform group count even when empty

        const uint32_t baseA = sb + (kc % 3) * 32768;
        const uint32_t baseB = baseA + 16384;

        #pragma unroll
        for (int ks = 0; ks < 4; ks++) {   // four k32 steps per 128-B chunk
            uint32_t a[4][4], b[2][4];
            #pragma unroll
            for (int mt = 0; mt < 4; mt++) {
                const int row = warp_m * 64 + mt * 16 + (lane & 15);
                const int chunk = ks * 2 + (lane >> 4);
                LDSM_X4(a[mt][0], a[mt][1], a[mt][2], a[mt][3],
                        baseA + row * 128 + ((chunk ^ (row & 7)) << 4));
            }
            #pragma unroll
            for (int nt = 0; nt < 2; nt++) {
                const int row = warp_n * 32 + nt * 16 + (lane & 15);
                const int chunk = ks * 2 + (lane >> 4);
                LDSM_X4(b[nt][0], b[nt][1], b[nt][2], b[nt][3],
                        baseB + row * 128 + ((chunk ^ (row & 7)) << 4));
            }
            #pragma unroll
            for (int mt = 0; mt < 4; mt++)
                #pragma unroll
                for (int nt = 0; nt < 4; nt++)
                    mma16832_s8(acc[mt][nt], a[mt],
                                b[nt >> 1][nt & 1], b[nt >> 1][(nt & 1) + 2]);
        }
    }

    // ---- fused hinge epilogue: score = acc / QSCALE^2 ----
    const float inv_s2 = 1.0f / (QSCALE * QSCALE);
    float partial = 0.f;
    #pragma unroll
    for (int mt = 0; mt < 4; mt++) {
        const int r0 = blockIdx.y * 128 + warp_m * 64 + mt * 16 + (lane >> 2);
        const float p0 = __ldg(&g_pos[r0]) - 1.0f;   // v - pos + 1 = v - (pos-1)
        const float p1 = __ldg(&g_pos[r0 + 8]) - 1.0f;
        #pragma unroll
        for (int nt = 0; nt < 4; nt++) {
            partial += fmaxf((float)acc[mt][nt][0] * inv_s2 - p0, 0.f);
            partial += fmaxf((float)acc[mt][nt][1] * inv_s2 - p0, 0.f);
            partial += fmaxf((float)acc[mt][nt][2] * inv_s2 - p1, 0.f);
            partial += fmaxf((float)acc[mt][nt][3] * inv_s2 - p1, 0.f);
        }
    }

    #pragma unroll
    for (int o = 16; o > 0; o >>= 1)
        partial += __shfl_xor_sync(0xFFFFFFFFu, partial, o);
    __shared__ float warpsum[8];
    if (lane == 0) warpsum[wid] = partial;
    __syncthreads();
    if (tid == 0) {
        float s = 0.f;
        #pragma unroll
        for (int w = 0; w < 8; w++) s += warpsum[w];
        atomicAdd(&g_glob, (double)s);
    }
}

// ---------------------------------------------------------------------------
__global__ void finalize_kernel(float* out) {
    out[0] = (float)(g_glob - g_local / (double)L_DIM);
}

// ---------------------------------------------------------------------------
extern "C" void kernel_launch(void* const* d_in, const int* in_sizes, int n_in,
                              void* d_out, int out_size) {
    const float* q_hat  = (const float*)d_in[0];
    const float* q_real = (const float*)d_in[1];
    const float* gt     = (const float*)d_in[2];
    const float* pred   = (const float*)d_in[3];

    (void)in_sizes; (void)n_in; (void)out_size;

    // One-time setup on the first (non-captured) correctness call.
    static cudaStream_t s_side = nullptr;
    static cudaEvent_t ev_fork = nullptr, ev_join = nullptr;
    static bool init_done = false;
    if (!init_done) {
        cudaFuncSetAttribute(gemm_hinge_kernel,
                             cudaFuncAttributeMaxDynamicSharedMemorySize,
                             GEMM_SMEM_DYN);
        cudaStreamCreateWithFlags(&s_side, cudaStreamNonBlocking);
        cudaEventCreateWithFlags(&ev_fork, cudaEventDisableTiming);
        cudaEventCreateWithFlags(&ev_join, cudaEventDisableTiming);
        init_done = true;
    }

    // Main (captured) stream: zero -> prep -> gemm -> finalize
    // Side stream: local_kernel (independent; overlaps prep + gemm)
    zero_kernel<<<1, 1>>>();
    cudaEventRecord(ev_fork, 0);
    cudaStreamWaitEvent(s_side, ev_fork, 0);

    prep_kernel<<<B_DIM, 256>>>(pred, gt);
    local_kernel<<<1024, 256, 0, s_side>>>(q_hat, q_real);

    gemm_hinge_kernel<<<dim3(32, 32), 256, GEMM_SMEM_DYN>>>();

    cudaEventRecord(ev_join, s_side);
    cudaStreamWaitEvent(0, ev_join, 0);
    finalize_kernel<<<1, 1>>>((float*)d_out);
}

// round 6
// speedup vs baseline: 1.7099x; 1.7099x over previous
#include <cuda_runtime.h>
#include <cuda_bf16.h>
#include <cstdint>

// ---------------------------------------------------------------------------
// total = -(1/L) * sum_i dot(q_hat_i, q_real_i)
//       + sum_{i,j} max(0, <pred_i, gt_j> - <pred_i, gt_i> + 1)
// L=8192, B=4096, D=1024.
// R6: back to FP8 e4m3 mma.sync.m16n8k32 (s8 runs at 1/4 rate on sm_103 —
// R5 evidence). GEMM reshaped to 512 threads / warp tile 32x32 so regs drop
// ~108 -> ~60 and 2 CTAs/SM = 8 warps/SMSP hide LDSM latency.
// local_kernel overlapped on a side stream.
// ---------------------------------------------------------------------------

#define L_DIM 8192
#define B_DIM 4096
#define D_DIM 1024

__device__ double g_glob;
__device__ double g_local;
__device__ float g_pos[B_DIM];
// FP8 operand buffers (4 MB each), stored as uint32 (4 e4m3 per word)
__device__ uint32_t g_predq[(size_t)B_DIM * D_DIM / 4];
__device__ uint32_t g_gtq[(size_t)B_DIM * D_DIM / 4];

// ---------------------------------------------------------------------------
__device__ __forceinline__ uint32_t smem_u32(const void* p) {
    uint32_t a;
    asm("{ .reg .u64 t; cvta.to.shared.u64 t, %1; cvt.u32.u64 %0, t; }"
        : "=r"(a) : "l"(p));
    return a;
}

__device__ __forceinline__ void cp_async16(uint32_t smem, const void* gmem) {
    asm volatile("cp.async.cg.shared.global [%0], [%1], 16;"
                 :: "r"(smem), "l"(gmem) : "memory");
}
#define CP_COMMIT() asm volatile("cp.async.commit_group;" ::: "memory")
#define CP_WAIT1()  asm volatile("cp.async.wait_group 1;" ::: "memory")

#define LDSM_X4(r0, r1, r2, r3, addr) \
    asm volatile("ldmatrix.sync.aligned.m8n8.x4.shared.b16 {%0,%1,%2,%3}, [%4];" \
                 : "=r"(r0), "=r"(r1), "=r"(r2), "=r"(r3) : "r"(addr))

// FP8 e4m3 MMA, k32, fp32 accumulation.
__device__ __forceinline__ void mma16832(float* c, const uint32_t* a,
                                         uint32_t b0, uint32_t b1) {
    asm volatile(
        "mma.sync.aligned.m16n8k32.row.col.f32.e4m3.e4m3.f32 "
        "{%0,%1,%2,%3}, {%4,%5,%6,%7}, {%8,%9}, {%0,%1,%2,%3};"
        : "+f"(c[0]), "+f"(c[1]), "+f"(c[2]), "+f"(c[3])
        : "r"(a[0]), "r"(a[1]), "r"(a[2]), "r"(a[3]), "r"(b0), "r"(b1));
}

__device__ __forceinline__ uint32_t pack_e4m3x4(float4 v) {
    uint16_t lo, hi;
    asm("cvt.rn.satfinite.e4m3x2.f32 %0, %1, %2;" : "=h"(lo) : "f"(v.y), "f"(v.x));
    asm("cvt.rn.satfinite.e4m3x2.f32 %0, %1, %2;" : "=h"(hi) : "f"(v.w), "f"(v.z));
    return (uint32_t)lo | ((uint32_t)hi << 16);
}

// ---------------------------------------------------------------------------
// Kernel 0: zero accumulators (must precede the forked local_kernel)
// ---------------------------------------------------------------------------
__global__ void zero_kernel() {
    g_glob = 0.0;
    g_local = 0.0;
}

// ---------------------------------------------------------------------------
// Kernel 1: fp32 -> e4m3 for pred/gt + pos[i] = dot(pred_i, gt_i) (exact fp32)
// ---------------------------------------------------------------------------
__global__ void prep_kernel(const float* __restrict__ pred,
                            const float* __restrict__ gt) {
    const int r = blockIdx.x;
    const int t = threadIdx.x;
    const float4 pv = ((const float4*)(pred + (size_t)r * D_DIM))[t];
    const float4 gv = ((const float4*)(gt + (size_t)r * D_DIM))[t];

    float acc = pv.x * gv.x + pv.y * gv.y + pv.z * gv.z + pv.w * gv.w;

    g_predq[(size_t)r * (D_DIM / 4) + t] = pack_e4m3x4(pv);
    g_gtq[(size_t)r * (D_DIM / 4) + t] = pack_e4m3x4(gv);

    #pragma unroll
    for (int o = 16; o > 0; o >>= 1)
        acc += __shfl_xor_sync(0xFFFFFFFFu, acc, o);
    __shared__ float ws[8];
    if ((t & 31) == 0) ws[t >> 5] = acc;
    __syncthreads();
    if (t == 0) {
        float s = 0.f;
        #pragma unroll
        for (int w = 0; w < 8; w++) s += ws[w];
        g_pos[r] = s;
    }
}

// ---------------------------------------------------------------------------
// Kernel 2: local loss partial (side stream; overlaps prep + GEMM)
// ---------------------------------------------------------------------------
__global__ void local_kernel(const float* __restrict__ a,
                             const float* __restrict__ b) {
    const size_t n4 = (size_t)L_DIM * D_DIM / 4;
    float acc = 0.f;
    for (size_t i = (size_t)blockIdx.x * blockDim.x + threadIdx.x; i < n4;
         i += (size_t)gridDim.x * blockDim.x) {
        float4 av = ((const float4*)a)[i];
        float4 bv = ((const float4*)b)[i];
        acc += av.x * bv.x + av.y * bv.y + av.z * bv.z + av.w * bv.w;
    }
    #pragma unroll
    for (int o = 16; o > 0; o >>= 1)
        acc += __shfl_xor_sync(0xFFFFFFFFu, acc, o);
    __shared__ float ws[8];
    const int t = threadIdx.x;
    if ((t & 31) == 0) ws[t >> 5] = acc;
    __syncthreads();
    if (t == 0) {
        float s = 0.f;
        #pragma unroll
        for (int w = 0; w < 8; w++) s += ws[w];
        atomicAdd(&g_local, (double)s);
    }
}

// ---------------------------------------------------------------------------
// Kernel 3: FP8 GEMM 128x128 tile + fused hinge.
// grid = (32, 32), 512 threads (16 warps: 4(m) x 4(n), warp tile 32x32).
// BK = 128 fp8 = 128 B/row -> 16 KB per operand stage, 3 stages, 8 K-chunks.
// XOR swizzle. ~60 regs -> 2 CTAs/SM = 8 warps/SMSP.
// ---------------------------------------------------------------------------
static constexpr int GEMM_SMEM_DYN = 3 * 32768;  // 96 KB

__global__ void __launch_bounds__(512, 2) gemm_hinge_kernel() {
    extern __shared__ char smem_raw[];
    const uint32_t sb = smem_u32(smem_raw);
    const int tid = threadIdx.x;
    const int wid = tid >> 5;
    const int lane = tid & 31;
    const int warp_m = wid >> 2;   // 0..3
    const int warp_n = wid & 3;    // 0..3

    const uint8_t* __restrict__ Ab =
        (const uint8_t*)g_predq + (size_t)blockIdx.y * 128 * D_DIM;
    const uint8_t* __restrict__ Bb =
        (const uint8_t*)g_gtq + (size_t)blockIdx.x * 128 * D_DIM;

    float acc[2][4][4];
    #pragma unroll
    for (int i = 0; i < 2; i++)
        #pragma unroll
        for (int j = 0; j < 4; j++)
            #pragma unroll
            for (int e = 0; e < 4; e++) acc[i][j][e] = 0.f;

    // Load one K-chunk (128 B per row) of A and B into stage st.
    auto load_stage = [&](int kc, int st) {
        const uint32_t baseA = sb + st * 32768;
        const uint32_t baseB = baseA + 16384;
        #pragma unroll
        for (int i = 0; i < 2; i++) {
            const int idx = tid + i * 512;      // 0..1023
            const int row = idx >> 3;           // 0..127
            const int c = idx & 7;              // 16B chunk within 128B row
            const uint32_t soff = row * 128 + ((c ^ (row & 7)) << 4);
            cp_async16(baseA + soff, Ab + (size_t)row * D_DIM + kc * 128 + c * 16);
            cp_async16(baseB + soff, Bb + (size_t)row * D_DIM + kc * 128 + c * 16);
        }
    };

    load_stage(0, 0); CP_COMMIT();
    load_stage(1, 1); CP_COMMIT();

    #pragma unroll 1
    for (int kc = 0; kc < 8; ++kc) {
        CP_WAIT1();          // stage kc resident
        __syncthreads();     // all warps done with the stage we refill
        if (kc + 2 < 8) load_stage(kc + 2, (kc + 2) % 3);
        CP_COMMIT();         // uniform group count even when empty

        const uint32_t baseA = sb + (kc % 3) * 32768;
        const uint32_t baseB = baseA + 16384;

        #pragma unroll
        for (int ks = 0; ks < 4; ks++) {   // four k32 steps per 128-B chunk
            uint32_t a[2][4], b[2][4];
            #pragma unroll
            for (int mt = 0; mt < 2; mt++) {
                const int row = warp_m * 32 + mt * 16 + (lane & 15);
                const int chunk = ks * 2 + (lane >> 4);
                LDSM_X4(a[mt][0], a[mt][1], a[mt][2], a[mt][3],
                        baseA + row * 128 + ((chunk ^ (row & 7)) << 4));
            }
            #pragma unroll
            for (int nt = 0; nt < 2; nt++) {
                const int row = warp_n * 32 + nt * 16 + (lane & 15);
                const int chunk = ks * 2 + (lane >> 4);
                LDSM_X4(b[nt][0], b[nt][1], b[nt][2], b[nt][3],
                        baseB + row * 128 + ((chunk ^ (row & 7)) << 4));
            }
            #pragma unroll
            for (int mt = 0; mt < 2; mt++)
                #pragma unroll
                for (int nt = 0; nt < 4; nt++)
                    mma16832(acc[mt][nt], a[mt],
                             b[nt >> 1][nt & 1], b[nt >> 1][(nt & 1) + 2]);
        }
    }

    // ---- fused hinge epilogue ----
    float partial = 0.f;
    #pragma unroll
    for (int mt = 0; mt < 2; mt++) {
        const int r0 = blockIdx.y * 128 + warp_m * 32 + mt * 16 + (lane >> 2);
        const float p0 = __ldg(&g_pos[r0]) - 1.0f;   // v - pos + 1 = v - (pos-1)
        const float p1 = __ldg(&g_pos[r0 + 8]) - 1.0f;
        #pragma unroll
        for (int nt = 0; nt < 4; nt++) {
            partial += fmaxf(acc[mt][nt][0] - p0, 0.f);
            partial += fmaxf(acc[mt][nt][1] - p0, 0.f);
            partial += fmaxf(acc[mt][nt][2] - p1, 0.f);
            partial += fmaxf(acc[mt][nt][3] - p1, 0.f);
        }
    }

    #pragma unroll
    for (int o = 16; o > 0; o >>= 1)
        partial += __shfl_xor_sync(0xFFFFFFFFu, partial, o);
    __shared__ float warpsum[16];
    if (lane == 0) warpsum[wid] = partial;
    __syncthreads();
    if (tid == 0) {
        float s = 0.f;
        #pragma unroll
        for (int w = 0; w < 16; w++) s += warpsum[w];
        atomicAdd(&g_glob, (double)s);
    }
}

// ---------------------------------------------------------------------------
__global__ void finalize_kernel(float* out) {
    out[0] = (float)(g_glob - g_local / (double)L_DIM);
}

// ---------------------------------------------------------------------------
extern "C" void kernel_launch(void* const* d_in, const int* in_sizes, int n_in,
                              void* d_out, int out_size) {
    const float* q_hat  = (const float*)d_in[0];
    const float* q_real = (const float*)d_in[1];
    const float* gt     = (const float*)d_in[2];
    const float* pred   = (const float*)d_in[3];

    (void)in_sizes; (void)n_in; (void)out_size;

    // One-time setup on the first (non-captured) correctness call.
    static cudaStream_t s_side = nullptr;
    static cudaEvent_t ev_fork = nullptr, ev_join = nullptr;
    static bool init_done = false;
    if (!init_done) {
        cudaFuncSetAttribute(gemm_hinge_kernel,
                             cudaFuncAttributeMaxDynamicSharedMemorySize,
                             GEMM_SMEM_DYN);
        cudaStreamCreateWithFlags(&s_side, cudaStreamNonBlocking);
        cudaEventCreateWithFlags(&ev_fork, cudaEventDisableTiming);
        cudaEventCreateWithFlags(&ev_join, cudaEventDisableTiming);
        init_done = true;
    }

    // Main (captured) stream: zero -> prep -> gemm -> finalize
    // Side stream: local_kernel (independent; overlaps prep + gemm)
    zero_kernel<<<1, 1>>>();
    cudaEventRecord(ev_fork, 0);
    cudaStreamWaitEvent(s_side, ev_fork, 0);

    prep_kernel<<<B_DIM, 256>>>(pred, gt);
    local_kernel<<<1024, 256, 0, s_side>>>(q_hat, q_real);

    gemm_hinge_kernel<<<dim3(32, 32), 512, GEMM_SMEM_DYN>>>();

    cudaEventRecord(ev_join, s_side);
    cudaStreamWaitEvent(0, ev_join, 0);
    finalize_kernel<<<1, 1>>>((float*)d_out);
}

// round 7
// speedup vs baseline: 2.1268x; 1.2438x over previous
#include <cuda_runtime.h>
#include <cuda_bf16.h>
#include <cstdint>

// ---------------------------------------------------------------------------
// total = -(1/L) * sum_i dot(q_hat_i, q_real_i)
//       + sum_{i,j} max(0, <pred_i, gt_j> - <pred_i, gt_i> + 1)
// L=8192, B=4096, D=1024.
// R7: R4 GEMM shape (256 thr, warp tile 64x32, fp8 e4m3, 3-stage, 2 CTA/SM)
// + ks-level fragment double-buffering (LDSM of ks+1 issued under MMAs of ks)
// + precomputed swizzle offsets. local_kernel overlapped on a side stream.
// ---------------------------------------------------------------------------

#define L_DIM 8192
#define B_DIM 4096
#define D_DIM 1024

__device__ double g_glob;
__device__ double g_local;
__device__ float g_pos[B_DIM];
// FP8 operand buffers (4 MB each), stored as uint32 (4 e4m3 per word)
__device__ uint32_t g_predq[(size_t)B_DIM * D_DIM / 4];
__device__ uint32_t g_gtq[(size_t)B_DIM * D_DIM / 4];

// ---------------------------------------------------------------------------
__device__ __forceinline__ uint32_t smem_u32(const void* p) {
    uint32_t a;
    asm("{ .reg .u64 t; cvta.to.shared.u64 t, %1; cvt.u32.u64 %0, t; }"
        : "=r"(a) : "l"(p));
    return a;
}

__device__ __forceinline__ void cp_async16(uint32_t smem, const void* gmem) {
    asm volatile("cp.async.cg.shared.global [%0], [%1], 16;"
                 :: "r"(smem), "l"(gmem) : "memory");
}
#define CP_COMMIT() asm volatile("cp.async.commit_group;" ::: "memory")
#define CP_WAIT1()  asm volatile("cp.async.wait_group 1;" ::: "memory")

#define LDSM_X4(r0, r1, r2, r3, addr) \
    asm volatile("ldmatrix.sync.aligned.m8n8.x4.shared.b16 {%0,%1,%2,%3}, [%4];" \
                 : "=r"(r0), "=r"(r1), "=r"(r2), "=r"(r3) : "r"(addr))

// FP8 e4m3 MMA, k32, fp32 accumulation.
__device__ __forceinline__ void mma16832(float* c, const uint32_t* a,
                                         uint32_t b0, uint32_t b1) {
    asm volatile(
        "mma.sync.aligned.m16n8k32.row.col.f32.e4m3.e4m3.f32 "
        "{%0,%1,%2,%3}, {%4,%5,%6,%7}, {%8,%9}, {%0,%1,%2,%3};"
        : "+f"(c[0]), "+f"(c[1]), "+f"(c[2]), "+f"(c[3])
        : "r"(a[0]), "r"(a[1]), "r"(a[2]), "r"(a[3]), "r"(b0), "r"(b1));
}

__device__ __forceinline__ uint32_t pack_e4m3x4(float4 v) {
    uint16_t lo, hi;
    asm("cvt.rn.satfinite.e4m3x2.f32 %0, %1, %2;" : "=h"(lo) : "f"(v.y), "f"(v.x));
    asm("cvt.rn.satfinite.e4m3x2.f32 %0, %1, %2;" : "=h"(hi) : "f"(v.w), "f"(v.z));
    return (uint32_t)lo | ((uint32_t)hi << 16);
}

// ---------------------------------------------------------------------------
// Kernel 0: zero accumulators (must precede the forked local_kernel)
// ---------------------------------------------------------------------------
__global__ void zero_kernel() {
    g_glob = 0.0;
    g_local = 0.0;
}

// ---------------------------------------------------------------------------
// Kernel 1: fp32 -> e4m3 for pred/gt + pos[i] = dot(pred_i, gt_i) (exact fp32)
// ---------------------------------------------------------------------------
__global__ void prep_kernel(const float* __restrict__ pred,
                            const float* __restrict__ gt) {
    const int r = blockIdx.x;
    const int t = threadIdx.x;
    const float4 pv = ((const float4*)(pred + (size_t)r * D_DIM))[t];
    const float4 gv = ((const float4*)(gt + (size_t)r * D_DIM))[t];

    float acc = pv.x * gv.x + pv.y * gv.y + pv.z * gv.z + pv.w * gv.w;

    g_predq[(size_t)r * (D_DIM / 4) + t] = pack_e4m3x4(pv);
    g_gtq[(size_t)r * (D_DIM / 4) + t] = pack_e4m3x4(gv);

    #pragma unroll
    for (int o = 16; o > 0; o >>= 1)
        acc += __shfl_xor_sync(0xFFFFFFFFu, acc, o);
    __shared__ float ws[8];
    if ((t & 31) == 0) ws[t >> 5] = acc;
    __syncthreads();
    if (t == 0) {
        float s = 0.f;
        #pragma unroll
        for (int w = 0; w < 8; w++) s += ws[w];
        g_pos[r] = s;
    }
}

// ---------------------------------------------------------------------------
// Kernel 2: local loss partial (side stream; overlaps prep + GEMM)
// ---------------------------------------------------------------------------
__global__ void local_kernel(const float* __restrict__ a,
                             const float* __restrict__ b) {
    const size_t n4 = (size_t)L_DIM * D_DIM / 4;
    float acc = 0.f;
    for (size_t i = (size_t)blockIdx.x * blockDim.x + threadIdx.x; i < n4;
         i += (size_t)gridDim.x * blockDim.x) {
        float4 av = ((const float4*)a)[i];
        float4 bv = ((const float4*)b)[i];
        acc += av.x * bv.x + av.y * bv.y + av.z * bv.z + av.w * bv.w;
    }
    #pragma unroll
    for (int o = 16; o > 0; o >>= 1)
        acc += __shfl_xor_sync(0xFFFFFFFFu, acc, o);
    __shared__ float ws[8];
    const int t = threadIdx.x;
    if ((t & 31) == 0) ws[t >> 5] = acc;
    __syncthreads();
    if (t == 0) {
        float s = 0.f;
        #pragma unroll
        for (int w = 0; w < 8; w++) s += ws[w];
        atomicAdd(&g_local, (double)s);
    }
}

// ---------------------------------------------------------------------------
// Kernel 3: FP8 GEMM 128x128 tile + fused hinge.
// grid = (32, 32), 256 threads (8 warps: 2(m) x 4(n), warp tile 64x32).
// BK = 128 fp8 = 128 B/row -> 16 KB/operand/stage, 3 stages, 8 K-chunks.
// ks-level fragment double buffering; 2 CTAs/SM.
// ---------------------------------------------------------------------------
static constexpr int GEMM_SMEM_DYN = 3 * 32768;  // 96 KB

__global__ void __launch_bounds__(256, 2) gemm_hinge_kernel() {
    extern __shared__ char smem_raw[];
    const uint32_t sb = smem_u32(smem_raw);
    const int tid = threadIdx.x;
    const int wid = tid >> 5;
    const int lane = tid & 31;
    const int warp_m = wid >> 2;   // 0..1
    const int warp_n = wid & 3;    // 0..3

    const uint8_t* __restrict__ Ab =
        (const uint8_t*)g_predq + (size_t)blockIdx.y * 128 * D_DIM;
    const uint8_t* __restrict__ Bb =
        (const uint8_t*)g_gtq + (size_t)blockIdx.x * 128 * D_DIM;

    // Precomputed LDSM offsets: addr = stage_base + off + ((c<<4) ^ xs)
    uint32_t a_off[4], a_xs[4], b_off[2], b_xs[2];
    #pragma unroll
    for (int mt = 0; mt < 4; mt++) {
        const int row = warp_m * 64 + mt * 16 + (lane & 15);
        a_off[mt] = row * 128;
        a_xs[mt] = (row & 7) << 4;
    }
    #pragma unroll
    for (int nt = 0; nt < 2; nt++) {
        const int row = warp_n * 32 + nt * 16 + (lane & 15);
        b_off[nt] = row * 128;
        b_xs[nt] = (row & 7) << 4;
    }
    const uint32_t c_lo = (uint32_t)(lane >> 4) << 4;  // 0 or 16

    float acc[4][4][4];
    #pragma unroll
    for (int i = 0; i < 4; i++)
        #pragma unroll
        for (int j = 0; j < 4; j++)
            #pragma unroll
            for (int e = 0; e < 4; e++) acc[i][j][e] = 0.f;

    // Load one K-chunk (128 B per row) of A and B into stage st.
    auto load_stage = [&](int kc, int st) {
        const uint32_t baseA = sb + st * 32768;
        const uint32_t baseB = baseA + 16384;
        #pragma unroll
        for (int i = 0; i < 4; i++) {
            const int idx = tid + i * 256;      // 0..1023
            const int row = idx >> 3;           // 0..127
            const int c = idx & 7;              // 16B chunk within 128B row
            const uint32_t soff = row * 128 + ((c ^ (row & 7)) << 4);
            cp_async16(baseA + soff, Ab + (size_t)row * D_DIM + kc * 128 + c * 16);
            cp_async16(baseB + soff, Bb + (size_t)row * D_DIM + kc * 128 + c * 16);
        }
    };

    load_stage(0, 0); CP_COMMIT();
    load_stage(1, 1); CP_COMMIT();

    uint32_t af[2][4][4], bf[2][2][4];

    // Loads the 6 fragments of one k32 step into buffer slot `buf`.
    auto load_frags = [&](int ks, int buf, uint32_t baseA, uint32_t baseB) {
        const uint32_t c4 = (uint32_t)(ks * 2) << 4;  // chunk byte offset
        #pragma unroll
        for (int mt = 0; mt < 4; mt++)
            LDSM_X4(af[buf][mt][0], af[buf][mt][1], af[buf][mt][2], af[buf][mt][3],
                    baseA + a_off[mt] + ((c4 + c_lo) ^ a_xs[mt]));
        #pragma unroll
        for (int nt = 0; nt < 2; nt++)
            LDSM_X4(bf[buf][nt][0], bf[buf][nt][1], bf[buf][nt][2], bf[buf][nt][3],
                    baseB + b_off[nt] + ((c4 + c_lo) ^ b_xs[nt]));
    };

    #pragma unroll 1
    for (int kc = 0; kc < 8; ++kc) {
        CP_WAIT1();          // stage kc resident
        __syncthreads();     // all warps done with the stage we refill
        if (kc + 2 < 8) load_stage(kc + 2, (kc + 2) % 3);
        CP_COMMIT();         // uniform group count even when empty

        const uint32_t baseA = sb + (kc % 3) * 32768;
        const uint32_t baseB = baseA + 16384;

        load_frags(0, 0, baseA, baseB);
        #pragma unroll
        for (int ks = 0; ks < 4; ks++) {
            const int cur = ks & 1;
            if (ks < 3) load_frags(ks + 1, cur ^ 1, baseA, baseB);
            #pragma unroll
            for (int mt = 0; mt < 4; mt++)
                #pragma unroll
                for (int nt = 0; nt < 4; nt++)
                    mma16832(acc[mt][nt], af[cur][mt],
                             bf[cur][nt >> 1][nt & 1], bf[cur][nt >> 1][(nt & 1) + 2]);
        }
    }

    // ---- fused hinge epilogue ----
    float partial = 0.f;
    #pragma unroll
    for (int mt = 0; mt < 4; mt++) {
        const int r0 = blockIdx.y * 128 + warp_m * 64 + mt * 16 + (lane >> 2);
        const float p0 = __ldg(&g_pos[r0]) - 1.0f;   // v - pos + 1 = v - (pos-1)
        const float p1 = __ldg(&g_pos[r0 + 8]) - 1.0f;
        #pragma unroll
        for (int nt = 0; nt < 4; nt++) {
            partial += fmaxf(acc[mt][nt][0] - p0, 0.f);
            partial += fmaxf(acc[mt][nt][1] - p0, 0.f);
            partial += fmaxf(acc[mt][nt][2] - p1, 0.f);
            partial += fmaxf(acc[mt][nt][3] - p1, 0.f);
        }
    }

    #pragma unroll
    for (int o = 16; o > 0; o >>= 1)
        partial += __shfl_xor_sync(0xFFFFFFFFu, partial, o);
    __shared__ float warpsum[8];
    if (lane == 0) warpsum[wid] = partial;
    __syncthreads();
    if (tid == 0) {
        float s = 0.f;
        #pragma unroll
        for (int w = 0; w < 8; w++) s += warpsum[w];
        atomicAdd(&g_glob, (double)s);
    }
}

// ---------------------------------------------------------------------------
__global__ void finalize_kernel(float* out) {
    out[0] = (float)(g_glob - g_local / (double)L_DIM);
}

// ---------------------------------------------------------------------------
extern "C" void kernel_launch(void* const* d_in, const int* in_sizes, int n_in,
                              void* d_out, int out_size) {
    const float* q_hat  = (const float*)d_in[0];
    const float* q_real = (const float*)d_in[1];
    const float* gt     = (const float*)d_in[2];
    const float* pred   = (const float*)d_in[3];

    (void)in_sizes; (void)n_in; (void)out_size;

    // One-time setup on the first (non-captured) correctness call.
    static cudaStream_t s_side = nullptr;
    static cudaEvent_t ev_fork = nullptr, ev_join = nullptr;
    static bool init_done = false;
    if (!init_done) {
        cudaFuncSetAttribute(gemm_hinge_kernel,
                             cudaFuncAttributeMaxDynamicSharedMemorySize,
                             GEMM_SMEM_DYN);
        cudaStreamCreateWithFlags(&s_side, cudaStreamNonBlocking);
        cudaEventCreateWithFlags(&ev_fork, cudaEventDisableTiming);
        cudaEventCreateWithFlags(&ev_join, cudaEventDisableTiming);
        init_done = true;
    }

    // Main (captured) stream: zero -> prep -> gemm -> finalize
    // Side stream: local_kernel (independent; overlaps prep + gemm)
    zero_kernel<<<1, 1>>>();
    cudaEventRecord(ev_fork, 0);
    cudaStreamWaitEvent(s_side, ev_fork, 0);

    prep_kernel<<<B_DIM, 256>>>(pred, gt);
    local_kernel<<<1024, 256, 0, s_side>>>(q_hat, q_real);

    gemm_hinge_kernel<<<dim3(32, 32), 256, GEMM_SMEM_DYN>>>();

    cudaEventRecord(ev_join, s_side);
    cudaStreamWaitEvent(0, ev_join, 0);
    finalize_kernel<<<1, 1>>>((float*)d_out);
}

// round 8
// speedup vs baseline: 2.2625x; 1.0638x over previous
#include <cuda_runtime.h>
#include <cuda_bf16.h>
#include <cstdint>

// ---------------------------------------------------------------------------
// total = -(1/L) * sum_i dot(q_hat_i, q_real_i)
//       + sum_{i,j} max(0, <pred_i, gt_j> - <pred_i, gt_i> + 1)
// L=8192, B=4096, D=1024.
// R8: R4 GEMM inner loop restored (single-buffered fragments; the R7 ks
// double-buffer hit the 128-reg cap and lost 9 us) + precomputed swizzle
// bases + side-stream local overlap + memset-based zeroing.
// ---------------------------------------------------------------------------

#define L_DIM 8192
#define B_DIM 4096
#define D_DIM 1024

__device__ double g_accum[2];   // [0]=glob, [1]=local  (memset to 0 each run)
__device__ float g_pos[B_DIM];
// FP8 operand buffers (4 MB each), stored as uint32 (4 e4m3 per word)
__device__ uint32_t g_predq[(size_t)B_DIM * D_DIM / 4];
__device__ uint32_t g_gtq[(size_t)B_DIM * D_DIM / 4];

// ---------------------------------------------------------------------------
__device__ __forceinline__ uint32_t smem_u32(const void* p) {
    uint32_t a;
    asm("{ .reg .u64 t; cvta.to.shared.u64 t, %1; cvt.u32.u64 %0, t; }"
        : "=r"(a) : "l"(p));
    return a;
}

__device__ __forceinline__ void cp_async16(uint32_t smem, const void* gmem) {
    asm volatile("cp.async.cg.shared.global [%0], [%1], 16;"
                 :: "r"(smem), "l"(gmem) : "memory");
}
#define CP_COMMIT() asm volatile("cp.async.commit_group;" ::: "memory")
#define CP_WAIT1()  asm volatile("cp.async.wait_group 1;" ::: "memory")

#define LDSM_X4(r0, r1, r2, r3, addr) \
    asm volatile("ldmatrix.sync.aligned.m8n8.x4.shared.b16 {%0,%1,%2,%3}, [%4];" \
                 : "=r"(r0), "=r"(r1), "=r"(r2), "=r"(r3) : "r"(addr))

// FP8 e4m3 MMA, k32, fp32 accumulation.
__device__ __forceinline__ void mma16832(float* c, const uint32_t* a,
                                         uint32_t b0, uint32_t b1) {
    asm volatile(
        "mma.sync.aligned.m16n8k32.row.col.f32.e4m3.e4m3.f32 "
        "{%0,%1,%2,%3}, {%4,%5,%6,%7}, {%8,%9}, {%0,%1,%2,%3};"
        : "+f"(c[0]), "+f"(c[1]), "+f"(c[2]), "+f"(c[3])
        : "r"(a[0]), "r"(a[1]), "r"(a[2]), "r"(a[3]), "r"(b0), "r"(b1));
}

__device__ __forceinline__ uint32_t pack_e4m3x4(float4 v) {
    uint16_t lo, hi;
    asm("cvt.rn.satfinite.e4m3x2.f32 %0, %1, %2;" : "=h"(lo) : "f"(v.y), "f"(v.x));
    asm("cvt.rn.satfinite.e4m3x2.f32 %0, %1, %2;" : "=h"(hi) : "f"(v.w), "f"(v.z));
    return (uint32_t)lo | ((uint32_t)hi << 16);
}

// ---------------------------------------------------------------------------
// Kernel 1: fp32 -> e4m3 for pred/gt + pos[i] = dot(pred_i, gt_i) (exact fp32)
// ---------------------------------------------------------------------------
__global__ void prep_kernel(const float* __restrict__ pred,
                            const float* __restrict__ gt) {
    const int r = blockIdx.x;
    const int t = threadIdx.x;
    const float4 pv = ((const float4*)(pred + (size_t)r * D_DIM))[t];
    const float4 gv = ((const float4*)(gt + (size_t)r * D_DIM))[t];

    float acc = pv.x * gv.x + pv.y * gv.y + pv.z * gv.z + pv.w * gv.w;

    g_predq[(size_t)r * (D_DIM / 4) + t] = pack_e4m3x4(pv);
    g_gtq[(size_t)r * (D_DIM / 4) + t] = pack_e4m3x4(gv);

    #pragma unroll
    for (int o = 16; o > 0; o >>= 1)
        acc += __shfl_xor_sync(0xFFFFFFFFu, acc, o);
    __shared__ float ws[8];
    if ((t & 31) == 0) ws[t >> 5] = acc;
    __syncthreads();
    if (t == 0) {
        float s = 0.f;
        #pragma unroll
        for (int w = 0; w < 8; w++) s += ws[w];
        g_pos[r] = s;
    }
}

// ---------------------------------------------------------------------------
// Kernel 2: local loss partial (side stream; overlaps prep + GEMM)
// ---------------------------------------------------------------------------
__global__ void local_kernel(const float* __restrict__ a,
                             const float* __restrict__ b) {
    const size_t n4 = (size_t)L_DIM * D_DIM / 4;
    float acc = 0.f;
    for (size_t i = (size_t)blockIdx.x * blockDim.x + threadIdx.x; i < n4;
         i += (size_t)gridDim.x * blockDim.x) {
        float4 av = ((const float4*)a)[i];
        float4 bv = ((const float4*)b)[i];
        acc += av.x * bv.x + av.y * bv.y + av.z * bv.z + av.w * bv.w;
    }
    #pragma unroll
    for (int o = 16; o > 0; o >>= 1)
        acc += __shfl_xor_sync(0xFFFFFFFFu, acc, o);
    __shared__ float ws[8];
    const int t = threadIdx.x;
    if ((t & 31) == 0) ws[t >> 5] = acc;
    __syncthreads();
    if (t == 0) {
        float s = 0.f;
        #pragma unroll
        for (int w = 0; w < 8; w++) s += ws[w];
        atomicAdd(&g_accum[1], (double)s);
    }
}

// ---------------------------------------------------------------------------
// Kernel 3: FP8 GEMM 128x128 tile + fused hinge.
// grid = (32, 32), 256 threads (8 warps: 2(m) x 4(n), warp tile 64x32).
// BK = 128 fp8 = 128 B/row -> 16 KB/operand/stage, 3 stages, 8 K-chunks.
// Single-buffered fragments (R4 form), precomputed swizzle bases. 2 CTAs/SM.
// ---------------------------------------------------------------------------
static constexpr int GEMM_SMEM_DYN = 3 * 32768;  // 96 KB

__global__ void __launch_bounds__(256, 2) gemm_hinge_kernel() {
    extern __shared__ char smem_raw[];
    const uint32_t sb = smem_u32(smem_raw);
    const int tid = threadIdx.x;
    const int wid = tid >> 5;
    const int lane = tid & 31;
    const int warp_m = wid >> 2;   // 0..1
    const int warp_n = wid & 3;    // 0..3

    const uint8_t* __restrict__ Ab =
        (const uint8_t*)g_predq + (size_t)blockIdx.y * 128 * D_DIM;
    const uint8_t* __restrict__ Bb =
        (const uint8_t*)g_gtq + (size_t)blockIdx.x * 128 * D_DIM;

    // Precomputed LDSM base offsets: addr = stage_base + base[mt] ^ (chunk<<4)
    // where base already folds in the row and the row-dependent XOR key.
    uint32_t a_base[4], b_base[2];
    #pragma unroll
    for (int mt = 0; mt < 4; mt++) {
        const int row = warp_m * 64 + mt * 16 + (lane & 15);
        a_base[mt] = row * 128 + (((lane >> 4) ^ (row & 7)) << 4);
    }
    #pragma unroll
    for (int nt = 0; nt < 2; nt++) {
        const int row = warp_n * 32 + nt * 16 + (lane & 15);
        b_base[nt] = row * 128 + (((lane >> 4) ^ (row & 7)) << 4);
    }

    float acc[4][4][4];
    #pragma unroll
    for (int i = 0; i < 4; i++)
        #pragma unroll
        for (int j = 0; j < 4; j++)
            #pragma unroll
            for (int e = 0; e < 4; e++) acc[i][j][e] = 0.f;

    // Load one K-chunk (128 B per row) of A and B into stage st.
    auto load_stage = [&](int kc, int st) {
        const uint32_t baseA = sb + st * 32768;
        const uint32_t baseB = baseA + 16384;
        #pragma unroll
        for (int i = 0; i < 4; i++) {
            const int idx = tid + i * 256;      // 0..1023
            const int row = idx >> 3;           // 0..127
            const int c = idx & 7;              // 16B chunk within 128B row
            const uint32_t soff = row * 128 + ((c ^ (row & 7)) << 4);
            cp_async16(baseA + soff, Ab + (size_t)row * D_DIM + kc * 128 + c * 16);
            cp_async16(baseB + soff, Bb + (size_t)row * D_DIM + kc * 128 + c * 16);
        }
    };

    load_stage(0, 0); CP_COMMIT();
    load_stage(1, 1); CP_COMMIT();

    #pragma unroll 1
    for (int kc = 0; kc < 8; ++kc) {
        CP_WAIT1();          // stage kc resident
        __syncthreads();     // all warps done with the stage we refill
        if (kc + 2 < 8) load_stage(kc + 2, (kc + 2) % 3);
        CP_COMMIT();         // uniform group count even when empty

        const uint32_t baseA = sb + (kc % 3) * 32768;
        const uint32_t baseB = baseA + 16384;

        #pragma unroll
        for (int ks = 0; ks < 4; ks++) {   // four k32 steps per 128-B chunk
            const uint32_t cx = (uint32_t)(ks * 2) << 4;  // chunk XOR offset
            uint32_t a[4][4], b[2][4];
            #pragma unroll
            for (int mt = 0; mt < 4; mt++)
                LDSM_X4(a[mt][0], a[mt][1], a[mt][2], a[mt][3],
                        baseA + (a_base[mt] ^ cx));
            #pragma unroll
            for (int nt = 0; nt < 2; nt++)
                LDSM_X4(b[nt][0], b[nt][1], b[nt][2], b[nt][3],
                        baseB + (b_base[nt] ^ cx));
            #pragma unroll
            for (int mt = 0; mt < 4; mt++)
                #pragma unroll
                for (int nt = 0; nt < 4; nt++)
                    mma16832(acc[mt][nt], a[mt],
                             b[nt >> 1][nt & 1], b[nt >> 1][(nt & 1) + 2]);
        }
    }

    // ---- fused hinge epilogue ----
    float partial = 0.f;
    #pragma unroll
    for (int mt = 0; mt < 4; mt++) {
        const int r0 = blockIdx.y * 128 + warp_m * 64 + mt * 16 + (lane >> 2);
        const float p0 = __ldg(&g_pos[r0]) - 1.0f;   // v - pos + 1 = v - (pos-1)
        const float p1 = __ldg(&g_pos[r0 + 8]) - 1.0f;
        #pragma unroll
        for (int nt = 0; nt < 4; nt++) {
            partial += fmaxf(acc[mt][nt][0] - p0, 0.f);
            partial += fmaxf(acc[mt][nt][1] - p0, 0.f);
            partial += fmaxf(acc[mt][nt][2] - p1, 0.f);
            partial += fmaxf(acc[mt][nt][3] - p1, 0.f);
        }
    }

    #pragma unroll
    for (int o = 16; o > 0; o >>= 1)
        partial += __shfl_xor_sync(0xFFFFFFFFu, partial, o);
    __shared__ float warpsum[8];
    if (lane == 0) warpsum[wid] = partial;
    __syncthreads();
    if (tid == 0) {
        float s = 0.f;
        #pragma unroll
        for (int w = 0; w < 8; w++) s += warpsum[w];
        atomicAdd(&g_accum[0], (double)s);
    }
}

// ---------------------------------------------------------------------------
__global__ void finalize_kernel(float* out) {
    out[0] = (float)(g_accum[0] - g_accum[1] / (double)L_DIM);
}

// ---------------------------------------------------------------------------
extern "C" void kernel_launch(void* const* d_in, const int* in_sizes, int n_in,
                              void* d_out, int out_size) {
    const float* q_hat  = (const float*)d_in[0];
    const float* q_real = (const float*)d_in[1];
    const float* gt     = (const float*)d_in[2];
    const float* pred   = (const float*)d_in[3];

    (void)in_sizes; (void)n_in; (void)out_size;

    // One-time setup on the first (non-captured) correctness call.
    static cudaStream_t s_side = nullptr;
    static cudaEvent_t ev_fork = nullptr, ev_join = nullptr;
    static void* accum_ptr = nullptr;
    if (!accum_ptr) {
        cudaFuncSetAttribute(gemm_hinge_kernel,
                             cudaFuncAttributeMaxDynamicSharedMemorySize,
                             GEMM_SMEM_DYN);
        cudaStreamCreateWithFlags(&s_side, cudaStreamNonBlocking);
        cudaEventCreateWithFlags(&ev_fork, cudaEventDisableTiming);
        cudaEventCreateWithFlags(&ev_join, cudaEventDisableTiming);
        cudaGetSymbolAddress(&accum_ptr, g_accum);
    }

    // Main stream: memset -> prep -> gemm -> (join) -> finalize
    // Side stream: local_kernel (independent; overlaps prep + gemm)
    cudaMemsetAsync(accum_ptr, 0, 2 * sizeof(double), 0);
    cudaEventRecord(ev_fork, 0);
    cudaStreamWaitEvent(s_side, ev_fork, 0);

    prep_kernel<<<B_DIM, 256>>>(pred, gt);
    local_kernel<<<1024, 256, 0, s_side>>>(q_hat, q_real);

    gemm_hinge_kernel<<<dim3(32, 32), 256, GEMM_SMEM_DYN>>>();

    cudaEventRecord(ev_join, s_side);
    cudaStreamWaitEvent(0, ev_join, 0);
    finalize_kernel<<<1, 1>>>((float*)d_out);
}